// round 6
// baseline (speedup 1.0000x reference)
#include <cuda_runtime.h>
#include <cuda_bf16.h>
#include <cstdint>

#define DIM   768
#define NH    12
#define HD    64
#define BATCH 8
#define SEQ   1024
#define M_TOT (BATCH * SEQ)   // 8192
#define QKV_N (3 * DIM)       // 2304

// Scratch (no allocation allowed in kernel_launch)
static __device__ float g_qkv[(size_t)M_TOT * QKV_N];
static __device__ __nv_bfloat16 g_xh[(size_t)M_TOT * DIM];
static __device__ __nv_bfloat16 g_xl[(size_t)M_TOT * DIM];
static __device__ __nv_bfloat16 g_qwh[(size_t)QKV_N * DIM];
static __device__ __nv_bfloat16 g_qwl[(size_t)QKV_N * DIM];
static __device__ __nv_bfloat16 g_pwh[(size_t)DIM * DIM];
static __device__ __nv_bfloat16 g_pwl[(size_t)DIM * DIM];
static __device__ __nv_bfloat16 g_ah[(size_t)M_TOT * DIM];
static __device__ __nv_bfloat16 g_al[(size_t)M_TOT * DIM];

// ---------------------------------------------------------------------------
// helpers
// ---------------------------------------------------------------------------
__device__ __forceinline__ uint32_t smem_u32(const void* p) {
    uint32_t a;
    asm("{ .reg .u64 t; cvta.to.shared.u64 t, %1; cvt.u32.u64 %0, t; }"
        : "=r"(a) : "l"(p));
    return a;
}
__device__ __forceinline__ void split1(float v, __nv_bfloat16& h, __nv_bfloat16& l) {
    h = __float2bfloat16(v);
    l = __float2bfloat16(v - __bfloat162float(h));
}
__device__ __forceinline__ uint32_t pack2(__nv_bfloat16 a, __nv_bfloat16 b) {
    return (uint32_t)__bfloat16_as_ushort(a) |
           ((uint32_t)__bfloat16_as_ushort(b) << 16);
}
__device__ __forceinline__ void split_pair(float a, float b,
                                           uint32_t& hi, uint32_t& lo) {
    __nv_bfloat16 ha, la, hb, lb;
    split1(a, ha, la); split1(b, hb, lb);
    hi = pack2(ha, hb); lo = pack2(la, lb);
}

#define LDX4(r, addr)                                                        \
    asm volatile("ldmatrix.sync.aligned.m8n8.x4.shared.b16 {%0,%1,%2,%3}, [%4];" \
        : "=r"((r)[0]), "=r"((r)[1]), "=r"((r)[2]), "=r"((r)[3])             \
        : "r"(addr))

#define LDX4T(r, addr)                                                       \
    asm volatile("ldmatrix.sync.aligned.m8n8.x4.trans.shared.b16 {%0,%1,%2,%3}, [%4];" \
        : "=r"((r)[0]), "=r"((r)[1]), "=r"((r)[2]), "=r"((r)[3])             \
        : "r"(addr))

#define MMA_BF16(c, a, b0, b1)                                               \
    asm volatile("mma.sync.aligned.m16n8k16.row.col.f32.bf16.bf16.f32 "      \
        "{%0,%1,%2,%3},{%4,%5,%6,%7},{%8,%9},{%0,%1,%2,%3};"                 \
        : "+f"((c)[0]), "+f"((c)[1]), "+f"((c)[2]), "+f"((c)[3])             \
        : "r"((a)[0]), "r"((a)[1]), "r"((a)[2]), "r"((a)[3]),                \
          "r"(b0), "r"(b1))

#define CP16(dst, src)                                                       \
    asm volatile("cp.async.ca.shared.global [%0], [%1], 16;"                 \
        :: "r"((uint32_t)(dst)), "l"(src))
#define CP_COMMIT() asm volatile("cp.async.commit_group;" ::: "memory")
#define CP_WAIT0()  asm volatile("cp.async.wait_group 0;" ::: "memory")

// ---------------------------------------------------------------------------
// f32 -> (hi, lo) bf16 split
// ---------------------------------------------------------------------------
__global__ void split_kernel(const float* __restrict__ in,
                             __nv_bfloat16* __restrict__ h,
                             __nv_bfloat16* __restrict__ l, int n)
{
    int i = (blockIdx.x * blockDim.x + threadIdx.x) * 4;
    if (i >= n) return;
    float4 v = *(const float4*)(in + i);
    uint32_t h0, l0, h1, l1;
    split_pair(v.x, v.y, h0, l0);
    split_pair(v.z, v.w, h1, l1);
    *(uint2*)(h + i) = make_uint2(h0, h1);
    *(uint2*)(l + i) = make_uint2(l0, l1);
}

// ---------------------------------------------------------------------------
// bf16 3-term GEMM v2: C[M,N] = A[M,K] @ W[N,K]^T + bias
// CTA 256x128, BK=32, 256 threads, 8 warps of 64x64 (4x2 warp grid).
// cp.async double-buffered smem, row stride 40 bf16 (conflict-free ldmatrix).
// ---------------------------------------------------------------------------
#define SB 40
#define A_BYTES (256 * SB * 2)        // 20480
#define B_BYTES (128 * SB * 2)        // 10240
#define BUFB (2 * A_BYTES + 2 * B_BYTES)   // Ah,Al,Bh,Bl = 61440
#define GEMM_SMEM (2 * BUFB)               // 122880

__global__ __launch_bounds__(256, 1) void gemm_bf16x3(
    const __nv_bfloat16* __restrict__ Ah, const __nv_bfloat16* __restrict__ Al,
    const __nv_bfloat16* __restrict__ Bh, const __nv_bfloat16* __restrict__ Bl,
    const float* __restrict__ bias, float* __restrict__ C, int N, int K)
{
    extern __shared__ __align__(16) char smraw[];
    const uint32_t sbase = smem_u32(smraw);

    const int tid  = threadIdx.x;
    const int wid  = tid >> 5;
    const int lane = tid & 31;
    const int wm   = wid & 3;        // 0..3 -> 64-row groups
    const int wn   = wid >> 2;       // 0..1 -> 64-col groups
    const int bm   = blockIdx.y * 256;
    const int bn   = blockIdx.x * 128;

    const uint32_t offA = (uint32_t)(lane & 15) * (SB * 2) + ((lane & 16) ? 16 : 0);
    const uint32_t offB = (uint32_t)(((lane & 16) >> 1) + (lane & 7)) * (SB * 2)
                        + ((lane & 8) ? 16 : 0);

    // cp.async source pointers
    const __nv_bfloat16* gAh = Ah + (size_t)(bm + tid) * K;
    const __nv_bfloat16* gAl = Al + (size_t)(bm + tid) * K;
    const int brow = tid >> 1;
    const int bp0  = (tid & 1) * 2;  // piece index base (2 pieces of 16B)
    const __nv_bfloat16* gBh = Bh + (size_t)(bn + brow) * K + bp0 * 8;
    const __nv_bfloat16* gBl = Bl + (size_t)(bn + brow) * K + bp0 * 8;
    const uint32_t dA  = (uint32_t)tid * (SB * 2);
    const uint32_t dB  = (uint32_t)brow * (SB * 2) + bp0 * 16;

    float acc[4][8][4];
#pragma unroll
    for (int t = 0; t < 4; t++)
#pragma unroll
        for (int u = 0; u < 8; u++)
#pragma unroll
            for (int j = 0; j < 4; j++) acc[t][u][j] = 0.f;

    const int nit = K / 32;

    // issue chunk c into buffer buf
    auto issue = [&](int c, int buf) {
        const uint32_t ab = sbase + buf * BUFB;
        const int k0 = c * 32;
#pragma unroll
        for (int p = 0; p < 4; p++) {
            CP16(ab + dA + p * 16,                       gAh + k0 + p * 8);
            CP16(ab + A_BYTES + dA + p * 16,             gAl + k0 + p * 8);
        }
#pragma unroll
        for (int p = 0; p < 2; p++) {
            CP16(ab + 2 * A_BYTES + dB + p * 16,             gBh + k0 + p * 8);
            CP16(ab + 2 * A_BYTES + B_BYTES + dB + p * 16,   gBl + k0 + p * 8);
        }
        CP_COMMIT();
    };

    issue(0, 0);

    for (int c = 0; c < nit; c++) {
        CP_WAIT0();
        __syncthreads();
        if (c + 1 < nit) issue(c + 1, (c + 1) & 1);

        const uint32_t ab  = sbase + (c & 1) * BUFB;
        const uint32_t uAh = ab;
        const uint32_t uAl = ab + A_BYTES;
        const uint32_t uBh = ab + 2 * A_BYTES;
        const uint32_t uBl = ab + 2 * A_BYTES + B_BYTES;

#pragma unroll
        for (int kk = 0; kk < 2; kk++) {
            uint32_t ah[4][4], al[4][4];
#pragma unroll
            for (int t = 0; t < 4; t++) {
                uint32_t a = (uint32_t)((wm * 64 + t * 16) * (SB * 2)) + kk * 32 + offA;
                LDX4(ah[t], uAh + a);
                LDX4(al[t], uAl + a);
            }
#pragma unroll
            for (int np = 0; np < 4; np++) {
                uint32_t bh[4], bl[4];
                uint32_t a = (uint32_t)((wn * 64 + np * 16) * (SB * 2)) + kk * 32 + offB;
                LDX4(bh, uBh + a);
                LDX4(bl, uBl + a);
#pragma unroll
                for (int t = 0; t < 4; t++) {
                    const int u = np * 2;
                    MMA_BF16(acc[t][u],     ah[t], bh[0], bh[1]);
                    MMA_BF16(acc[t][u],     ah[t], bl[0], bl[1]);
                    MMA_BF16(acc[t][u],     al[t], bh[0], bh[1]);
                    MMA_BF16(acc[t][u + 1], ah[t], bh[2], bh[3]);
                    MMA_BF16(acc[t][u + 1], ah[t], bl[2], bl[3]);
                    MMA_BF16(acc[t][u + 1], al[t], bh[2], bh[3]);
                }
            }
        }
        __syncthreads();
    }

    // Epilogue
    const int er = lane >> 2;
    const int ec = (lane & 3) * 2;
#pragma unroll
    for (int t = 0; t < 4; t++) {
        const int row = bm + wm * 64 + t * 16 + er;
#pragma unroll
        for (int u = 0; u < 8; u++) {
            const int col = bn + wn * 64 + u * 8 + ec;
            const float b0 = bias[col], b1 = bias[col + 1];
            float2 v0 = {acc[t][u][0] + b0, acc[t][u][1] + b1};
            float2 v1 = {acc[t][u][2] + b0, acc[t][u][3] + b1};
            *(float2*)&C[(size_t)row * N + col]       = v0;
            *(float2*)&C[(size_t)(row + 8) * N + col] = v1;
        }
    }
}

// ---------------------------------------------------------------------------
// Tensor-core flash attention v2: 256 threads, 128 q-rows/CTA (8 warps x 16).
// K/V staged once per 128 queries (halved staging vs round 5).
// ---------------------------------------------------------------------------
#define KSTR 72

__global__ __launch_bounds__(256) void attn_mma(const float* __restrict__ qkv,
                                                __nv_bfloat16* __restrict__ oh,
                                                __nv_bfloat16* __restrict__ ol)
{
    __shared__ __align__(16) __nv_bfloat16 sKh[64 * KSTR];
    __shared__ __align__(16) __nv_bfloat16 sKl[64 * KSTR];
    __shared__ __align__(16) __nv_bfloat16 sVh[64 * KSTR];
    __shared__ __align__(16) __nv_bfloat16 sVl[64 * KSTR];

    const int tid  = threadIdx.x;
    const int w    = tid >> 5;       // 0..7
    const int lane = tid & 31;
    const int qt   = blockIdx.x * 128;
    const int b    = blockIdx.y / NH;
    const int h    = blockIdx.y % NH;

    const float* base = qkv + (size_t)b * SEQ * QKV_N + h * HD;

    const uint32_t uKh = smem_u32(sKh), uKl = smem_u32(sKl);
    const uint32_t uVh = smem_u32(sVh), uVl = smem_u32(sVl);

    const uint32_t offA = (uint32_t)(lane & 15) * (KSTR * 2) + ((lane & 16) ? 16 : 0);
    const uint32_t offB = (uint32_t)(((lane & 16) >> 1) + (lane & 7)) * (KSTR * 2)
                        + ((lane & 8) ? 16 : 0);

    // staging mapping: row = tid/4 (0..63), 16-col quarter
    const int lr = tid >> 2;
    const int lc = (tid & 3) * 16;

    // ---- stage Q (scaled, split) in two 64-row halves; pull A-frags ----
    uint32_t qh[4][4], ql[4][4];
#pragma unroll
    for (int half = 0; half < 2; half++) {
        const float* qp = base + (size_t)(qt + half * 64 + lr) * QKV_N + lc;
        __nv_bfloat16* dh = &sKh[lr * KSTR + lc];
        __nv_bfloat16* dl = &sKl[lr * KSTR + lc];
#pragma unroll
        for (int j = 0; j < 4; j++) {
            float4 v = *(const float4*)(qp + j * 4);
            uint32_t h0, l0, h1, l1;
            split_pair(v.x * 0.125f, v.y * 0.125f, h0, l0);
            split_pair(v.z * 0.125f, v.w * 0.125f, h1, l1);
            *(uint2*)(dh + j * 4) = make_uint2(h0, h1);
            *(uint2*)(dl + j * 4) = make_uint2(l0, l1);
        }
        __syncthreads();
        if ((w >> 2) == half) {
#pragma unroll
            for (int ks = 0; ks < 4; ks++) {
                uint32_t a = (uint32_t)((w & 3) * 16) * (KSTR * 2) + ks * 32 + offA;
                LDX4(qh[ks], uKh + a);
                LDX4(ql[ks], uKl + a);
            }
        }
        __syncthreads();
    }

    float oacc[8][4];
#pragma unroll
    for (int u = 0; u < 8; u++)
#pragma unroll
        for (int j = 0; j < 4; j++) oacc[u][j] = 0.f;
    float m0 = -1e30f, m1 = -1e30f, l0 = 0.f, l1 = 0.f;

    for (int kt = 0; kt < SEQ / 64; kt++) {
        // ---- load K,V tiles (f32 -> hi/lo bf16), 16 elems/thread each ----
        {
            const float* kp = base + (size_t)(kt * 64 + lr) * QKV_N + DIM + lc;
            __nv_bfloat16* kh = &sKh[lr * KSTR + lc];
            __nv_bfloat16* kl = &sKl[lr * KSTR + lc];
            __nv_bfloat16* vh = &sVh[lr * KSTR + lc];
            __nv_bfloat16* vl = &sVl[lr * KSTR + lc];
#pragma unroll
            for (int j = 0; j < 4; j++) {
                float4 kv = *(const float4*)(kp + j * 4);
                float4 vv = *(const float4*)(kp + DIM + j * 4);
                uint32_t h0, lo0, h1, lo1;
                split_pair(kv.x, kv.y, h0, lo0);
                split_pair(kv.z, kv.w, h1, lo1);
                *(uint2*)(kh + j * 4) = make_uint2(h0, h1);
                *(uint2*)(kl + j * 4) = make_uint2(lo0, lo1);
                split_pair(vv.x, vv.y, h0, lo0);
                split_pair(vv.z, vv.w, h1, lo1);
                *(uint2*)(vh + j * 4) = make_uint2(h0, h1);
                *(uint2*)(vl + j * 4) = make_uint2(lo0, lo1);
            }
        }
        __syncthreads();

        // ---- S = Q @ K^T (3-term) ----
        float sacc[8][4];
#pragma unroll
        for (int u = 0; u < 8; u++)
#pragma unroll
            for (int j = 0; j < 4; j++) sacc[u][j] = 0.f;

#pragma unroll
        for (int ks = 0; ks < 4; ks++) {
#pragma unroll
            for (int np = 0; np < 4; np++) {
                uint32_t kh[4], kl[4];
                uint32_t a = (uint32_t)(np * 16) * (KSTR * 2) + ks * 32 + offB;
                LDX4(kh, uKh + a);
                LDX4(kl, uKl + a);
                const int u = np * 2;
                MMA_BF16(sacc[u],     qh[ks], kh[0], kh[1]);
                MMA_BF16(sacc[u],     qh[ks], kl[0], kl[1]);
                MMA_BF16(sacc[u],     ql[ks], kh[0], kh[1]);
                MMA_BF16(sacc[u + 1], qh[ks], kh[2], kh[3]);
                MMA_BF16(sacc[u + 1], qh[ks], kl[2], kl[3]);
                MMA_BF16(sacc[u + 1], ql[ks], kh[2], kh[3]);
            }
        }

        // ---- online softmax ----
        float mt0 = -1e30f, mt1 = -1e30f;
#pragma unroll
        for (int u = 0; u < 8; u++) {
            mt0 = fmaxf(mt0, fmaxf(sacc[u][0], sacc[u][1]));
            mt1 = fmaxf(mt1, fmaxf(sacc[u][2], sacc[u][3]));
        }
        mt0 = fmaxf(mt0, __shfl_xor_sync(0xffffffffu, mt0, 1));
        mt0 = fmaxf(mt0, __shfl_xor_sync(0xffffffffu, mt0, 2));
        mt1 = fmaxf(mt1, __shfl_xor_sync(0xffffffffu, mt1, 1));
        mt1 = fmaxf(mt1, __shfl_xor_sync(0xffffffffu, mt1, 2));

        const float mn0 = fmaxf(m0, mt0);
        const float mn1 = fmaxf(m1, mt1);
        const float a0 = __expf(m0 - mn0);
        const float a1 = __expf(m1 - mn1);

        float ls0 = 0.f, ls1 = 0.f;
#pragma unroll
        for (int u = 0; u < 8; u++) {
            sacc[u][0] = __expf(sacc[u][0] - mn0);
            sacc[u][1] = __expf(sacc[u][1] - mn0);
            sacc[u][2] = __expf(sacc[u][2] - mn1);
            sacc[u][3] = __expf(sacc[u][3] - mn1);
            ls0 += sacc[u][0] + sacc[u][1];
            ls1 += sacc[u][2] + sacc[u][3];
        }
        ls0 += __shfl_xor_sync(0xffffffffu, ls0, 1);
        ls0 += __shfl_xor_sync(0xffffffffu, ls0, 2);
        ls1 += __shfl_xor_sync(0xffffffffu, ls1, 1);
        ls1 += __shfl_xor_sync(0xffffffffu, ls1, 2);
        l0 = l0 * a0 + ls0;  m0 = mn0;
        l1 = l1 * a1 + ls1;  m1 = mn1;

#pragma unroll
        for (int u = 0; u < 8; u++) {
            oacc[u][0] *= a0; oacc[u][1] *= a0;
            oacc[u][2] *= a1; oacc[u][3] *= a1;
        }

        // ---- pack P into A-frags (hi/lo) ----
        uint32_t pah[4][4], pal[4][4];
#pragma unroll
        for (int t = 0; t < 4; t++) {
            split_pair(sacc[2 * t][0],     sacc[2 * t][1],     pah[t][0], pal[t][0]);
            split_pair(sacc[2 * t][2],     sacc[2 * t][3],     pah[t][1], pal[t][1]);
            split_pair(sacc[2 * t + 1][0], sacc[2 * t + 1][1], pah[t][2], pal[t][2]);
            split_pair(sacc[2 * t + 1][2], sacc[2 * t + 1][3], pah[t][3], pal[t][3]);
        }

        // ---- O += P @ V (3-term; V via ldmatrix.trans) ----
#pragma unroll
        for (int t = 0; t < 4; t++) {
#pragma unroll
            for (int nd = 0; nd < 4; nd++) {
                uint32_t vh[4], vl[4];
                uint32_t a = (uint32_t)(t * 16) * (KSTR * 2) + nd * 32 + offB;
                LDX4T(vh, uVh + a);
                LDX4T(vl, uVl + a);
                const int u = nd * 2;
                MMA_BF16(oacc[u],     pah[t], vh[0], vh[2]);
                MMA_BF16(oacc[u],     pah[t], vl[0], vl[2]);
                MMA_BF16(oacc[u],     pal[t], vh[0], vh[2]);
                MMA_BF16(oacc[u + 1], pah[t], vh[1], vh[3]);
                MMA_BF16(oacc[u + 1], pah[t], vl[1], vl[3]);
                MMA_BF16(oacc[u + 1], pal[t], vh[1], vh[3]);
            }
        }
        __syncthreads();
    }

    // ---- epilogue ----
    const float inv0 = 1.f / l0;
    const float inv1 = 1.f / l1;
    const int er = lane >> 2;
    const int ec = (lane & 3) * 2;
    const size_t tok0 = (size_t)b * SEQ + qt + w * 16 + er;
    const int colb = h * HD + ec;
#pragma unroll
    for (int u = 0; u < 8; u++) {
        const int col = colb + u * 8;
        uint32_t hp, lp;
        split_pair(oacc[u][0] * inv0, oacc[u][1] * inv0, hp, lp);
        *(uint32_t*)(oh + tok0 * DIM + col) = hp;
        *(uint32_t*)(ol + tok0 * DIM + col) = lp;
        split_pair(oacc[u][2] * inv1, oacc[u][3] * inv1, hp, lp);
        *(uint32_t*)(oh + (tok0 + 8) * DIM + col) = hp;
        *(uint32_t*)(ol + (tok0 + 8) * DIM + col) = lp;
    }
}

extern "C" void kernel_launch(void* const* d_in, const int* in_sizes, int n_in,
                              void* d_out, int out_size)
{
    const float* x      = (const float*)d_in[0];
    const float* qkv_w  = (const float*)d_in[1];
    const float* qkv_b  = (const float*)d_in[2];
    const float* proj_w = (const float*)d_in[3];
    const float* proj_b = (const float*)d_in[4];
    float* out = (float*)d_out;

    float* qkv;
    __nv_bfloat16 *xh, *xl, *qwh, *qwl, *pwh, *pwl, *ah, *al;
    cudaGetSymbolAddress((void**)&qkv, g_qkv);
    cudaGetSymbolAddress((void**)&xh,  g_xh);
    cudaGetSymbolAddress((void**)&xl,  g_xl);
    cudaGetSymbolAddress((void**)&qwh, g_qwh);
    cudaGetSymbolAddress((void**)&qwl, g_qwl);
    cudaGetSymbolAddress((void**)&pwh, g_pwh);
    cudaGetSymbolAddress((void**)&pwl, g_pwl);
    cudaGetSymbolAddress((void**)&ah,  g_ah);
    cudaGetSymbolAddress((void**)&al,  g_al);

    cudaFuncSetAttribute(gemm_bf16x3,
                         cudaFuncAttributeMaxDynamicSharedMemorySize, GEMM_SMEM);

    // splits
    const int nx = M_TOT * DIM, nqw = QKV_N * DIM, npw = DIM * DIM;
    split_kernel<<<(nx / 4 + 255) / 256, 256>>>(x, xh, xl, nx);
    split_kernel<<<(nqw / 4 + 255) / 256, 256>>>(qkv_w, qwh, qwl, nqw);
    split_kernel<<<(npw / 4 + 255) / 256, 256>>>(proj_w, pwh, pwl, npw);

    // QKV projection: [8192, 2304]
    gemm_bf16x3<<<dim3(QKV_N / 128, M_TOT / 256), 256, GEMM_SMEM>>>(
        xh, xl, qwh, qwl, qkv_b, qkv, QKV_N, DIM);

    // Attention (tensor-core) -> bf16 hi/lo
    attn_mma<<<dim3(SEQ / 128, BATCH * NH), 256>>>(qkv, ah, al);

    // Output projection: [8192, 768]
    gemm_bf16x3<<<dim3(DIM / 128, M_TOT / 256), 256, GEMM_SMEM>>>(
        ah, al, pwh, pwl, proj_b, out, DIM, DIM);
}

// round 8
// speedup vs baseline: 1.1521x; 1.1521x over previous
#include <cuda_runtime.h>
#include <cuda_bf16.h>
#include <cstdint>

#define DIM   768
#define NH    12
#define HD    64
#define BATCH 8
#define SEQ   1024
#define M_TOT (BATCH * SEQ)   // 8192
#define QKV_N (3 * DIM)       // 2304

// Scratch (no allocation allowed in kernel_launch)
static __device__ float g_qkv[(size_t)M_TOT * QKV_N];
static __device__ __nv_bfloat16 g_xh[(size_t)M_TOT * DIM];
static __device__ __nv_bfloat16 g_xl[(size_t)M_TOT * DIM];
static __device__ __nv_bfloat16 g_qwh[(size_t)QKV_N * DIM];
static __device__ __nv_bfloat16 g_qwl[(size_t)QKV_N * DIM];
static __device__ __nv_bfloat16 g_pwh[(size_t)DIM * DIM];
static __device__ __nv_bfloat16 g_pwl[(size_t)DIM * DIM];
static __device__ __nv_bfloat16 g_ah[(size_t)M_TOT * DIM];
static __device__ __nv_bfloat16 g_al[(size_t)M_TOT * DIM];

// ---------------------------------------------------------------------------
// helpers
// ---------------------------------------------------------------------------
__device__ __forceinline__ uint32_t smem_u32(const void* p) {
    uint32_t a;
    asm("{ .reg .u64 t; cvta.to.shared.u64 t, %1; cvt.u32.u64 %0, t; }"
        : "=r"(a) : "l"(p));
    return a;
}
__device__ __forceinline__ void split1(float v, __nv_bfloat16& h, __nv_bfloat16& l) {
    h = __float2bfloat16(v);
    l = __float2bfloat16(v - __bfloat162float(h));
}
__device__ __forceinline__ uint32_t pack2(__nv_bfloat16 a, __nv_bfloat16 b) {
    return (uint32_t)__bfloat16_as_ushort(a) |
           ((uint32_t)__bfloat16_as_ushort(b) << 16);
}
__device__ __forceinline__ void split_pair(float a, float b,
                                           uint32_t& hi, uint32_t& lo) {
    __nv_bfloat16 ha, la, hb, lb;
    split1(a, ha, la); split1(b, hb, lb);
    hi = pack2(ha, hb); lo = pack2(la, lb);
}

#define LDX4(r, addr)                                                        \
    asm volatile("ldmatrix.sync.aligned.m8n8.x4.shared.b16 {%0,%1,%2,%3}, [%4];" \
        : "=r"((r)[0]), "=r"((r)[1]), "=r"((r)[2]), "=r"((r)[3])             \
        : "r"(addr))

#define LDX4T(r, addr)                                                       \
    asm volatile("ldmatrix.sync.aligned.m8n8.x4.trans.shared.b16 {%0,%1,%2,%3}, [%4];" \
        : "=r"((r)[0]), "=r"((r)[1]), "=r"((r)[2]), "=r"((r)[3])             \
        : "r"(addr))

#define MMA_BF16(c, a, b0, b1)                                               \
    asm volatile("mma.sync.aligned.m16n8k16.row.col.f32.bf16.bf16.f32 "      \
        "{%0,%1,%2,%3},{%4,%5,%6,%7},{%8,%9},{%0,%1,%2,%3};"                 \
        : "+f"((c)[0]), "+f"((c)[1]), "+f"((c)[2]), "+f"((c)[3])             \
        : "r"((a)[0]), "r"((a)[1]), "r"((a)[2]), "r"((a)[3]),                \
          "r"(b0), "r"(b1))

// ---------------------------------------------------------------------------
// f32 -> (hi, lo) bf16 split
// ---------------------------------------------------------------------------
__global__ void split_kernel(const float* __restrict__ in,
                             __nv_bfloat16* __restrict__ h,
                             __nv_bfloat16* __restrict__ l, int n)
{
    int i = (blockIdx.x * blockDim.x + threadIdx.x) * 4;
    if (i >= n) return;
    float4 v = *(const float4*)(in + i);
    uint32_t h0, l0, h1, l1;
    split_pair(v.x, v.y, h0, l0);
    split_pair(v.z, v.w, h1, l1);
    *(uint2*)(h + i) = make_uint2(h0, h1);
    *(uint2*)(l + i) = make_uint2(l0, l1);
}

// ---------------------------------------------------------------------------
// bf16 3-term GEMM (round-5 version: 128x128 CTA, 8 warps of 64x32)
// ---------------------------------------------------------------------------
#define SB 40

__global__ __launch_bounds__(256) void gemm_bf16x3(
    const __nv_bfloat16* __restrict__ Ah, const __nv_bfloat16* __restrict__ Al,
    const __nv_bfloat16* __restrict__ Bh, const __nv_bfloat16* __restrict__ Bl,
    const float* __restrict__ bias, float* __restrict__ C, int N, int K)
{
    __shared__ __align__(16) __nv_bfloat16 sAh[128 * SB];
    __shared__ __align__(16) __nv_bfloat16 sAl[128 * SB];
    __shared__ __align__(16) __nv_bfloat16 sBh[128 * SB];
    __shared__ __align__(16) __nv_bfloat16 sBl[128 * SB];

    const int tid  = threadIdx.x;
    const int wid  = tid >> 5;
    const int lane = tid & 31;
    const int wm   = wid & 1;
    const int wn   = wid >> 1;
    const int bm   = blockIdx.y * 128;
    const int bn   = blockIdx.x * 128;

    const uint32_t uAh = smem_u32(sAh), uAl = smem_u32(sAl);
    const uint32_t uBh = smem_u32(sBh), uBl = smem_u32(sBl);

    const uint32_t offA = (uint32_t)(lane & 15) * (SB * 2) + ((lane & 16) ? 16 : 0);
    const uint32_t offB = (uint32_t)(((lane & 16) >> 1) + (lane & 7)) * (SB * 2)
                        + ((lane & 8) ? 16 : 0);

    const int lrow = tid >> 1;
    const int cb   = (tid & 1) * 16;
    const __nv_bfloat16* pAh = Ah + (size_t)(bm + lrow) * K + cb;
    const __nv_bfloat16* pAl = Al + (size_t)(bm + lrow) * K + cb;
    const __nv_bfloat16* pBh = Bh + (size_t)(bn + lrow) * K + cb;
    const __nv_bfloat16* pBl = Bl + (size_t)(bn + lrow) * K + cb;
    __nv_bfloat16* qAh = &sAh[lrow * SB + cb];
    __nv_bfloat16* qAl = &sAl[lrow * SB + cb];
    __nv_bfloat16* qBh = &sBh[lrow * SB + cb];
    __nv_bfloat16* qBl = &sBl[lrow * SB + cb];

    float acc[4][4][4];
#pragma unroll
    for (int t = 0; t < 4; t++)
#pragma unroll
        for (int u = 0; u < 4; u++)
#pragma unroll
            for (int j = 0; j < 4; j++) acc[t][u][j] = 0.f;

    const int nit = K / 32;
    uint4 rah0 = *(const uint4*)(pAh);     uint4 rah1 = *(const uint4*)(pAh + 8);
    uint4 ral0 = *(const uint4*)(pAl);     uint4 ral1 = *(const uint4*)(pAl + 8);
    uint4 rbh0 = *(const uint4*)(pBh);     uint4 rbh1 = *(const uint4*)(pBh + 8);
    uint4 rbl0 = *(const uint4*)(pBl);     uint4 rbl1 = *(const uint4*)(pBl + 8);

    for (int c = 0; c < nit; c++) {
        *(uint4*)(qAh) = rah0; *(uint4*)(qAh + 8) = rah1;
        *(uint4*)(qAl) = ral0; *(uint4*)(qAl + 8) = ral1;
        *(uint4*)(qBh) = rbh0; *(uint4*)(qBh + 8) = rbh1;
        *(uint4*)(qBl) = rbl0; *(uint4*)(qBl + 8) = rbl1;
        __syncthreads();

        if (c + 1 < nit) {
            const int k0 = (c + 1) * 32;
            rah0 = *(const uint4*)(pAh + k0); rah1 = *(const uint4*)(pAh + k0 + 8);
            ral0 = *(const uint4*)(pAl + k0); ral1 = *(const uint4*)(pAl + k0 + 8);
            rbh0 = *(const uint4*)(pBh + k0); rbh1 = *(const uint4*)(pBh + k0 + 8);
            rbl0 = *(const uint4*)(pBl + k0); rbl1 = *(const uint4*)(pBl + k0 + 8);
        }

#pragma unroll
        for (int kk = 0; kk < 32; kk += 16) {
            uint32_t ah[4][4], al[4][4], bh[2][4], bl[2][4];
#pragma unroll
            for (int t = 0; t < 4; t++) {
                uint32_t base = (uint32_t)((wm * 64 + t * 16) * (SB * 2)) + kk * 2;
                LDX4(ah[t], uAh + base + offA);
                LDX4(al[t], uAl + base + offA);
            }
#pragma unroll
            for (int p = 0; p < 2; p++) {
                uint32_t base = (uint32_t)((wn * 32 + p * 16) * (SB * 2)) + kk * 2;
                LDX4(bh[p], uBh + base + offB);
                LDX4(bl[p], uBl + base + offB);
            }
#pragma unroll
            for (int t = 0; t < 4; t++) {
#pragma unroll
                for (int u = 0; u < 4; u++) {
                    const int p = u >> 1, o = (u & 1) * 2;
                    MMA_BF16(acc[t][u], ah[t], bh[p][o], bh[p][o + 1]);
                    MMA_BF16(acc[t][u], ah[t], bl[p][o], bl[p][o + 1]);
                    MMA_BF16(acc[t][u], al[t], bh[p][o], bh[p][o + 1]);
                }
            }
        }
        __syncthreads();
    }

    const int er = lane >> 2;
    const int ec = (lane & 3) * 2;
#pragma unroll
    for (int t = 0; t < 4; t++) {
        const int row = bm + wm * 64 + t * 16 + er;
#pragma unroll
        for (int u = 0; u < 4; u++) {
            const int col = bn + wn * 32 + u * 8 + ec;
            const float b0 = bias[col], b1 = bias[col + 1];
            float2 v0 = {acc[t][u][0] + b0, acc[t][u][1] + b1};
            float2 v1 = {acc[t][u][2] + b0, acc[t][u][3] + b1};
            *(float2*)&C[(size_t)row * N + col]       = v0;
            *(float2*)&C[(size_t)(row + 8) * N + col] = v1;
        }
    }
}

// ---------------------------------------------------------------------------
// Tensor-core flash attention v3 (fixed): 128 thr, 64 q-rows, double-buffered
// K/V smem + register prefetch. Staging store stride = 8 bytes (uint2).
// ---------------------------------------------------------------------------
#define KSTR 72
#define ASZ  (64 * KSTR * 2)      // one array, bytes (9216)
#define BUFSZ (4 * ASZ)           // Kh,Kl,Vh,Vl (36864)
#define ATTN_SMEM (2 * BUFSZ)     // 73728

__global__ __launch_bounds__(128) void attn_mma(const float* __restrict__ qkv,
                                                __nv_bfloat16* __restrict__ oh,
                                                __nv_bfloat16* __restrict__ ol)
{
    extern __shared__ __align__(16) char smraw[];
    const uint32_t sb = smem_u32(smraw);

    const int tid  = threadIdx.x;
    const int w    = tid >> 5;
    const int lane = tid & 31;
    const int qt   = blockIdx.x * 64;
    const int b    = blockIdx.y / NH;
    const int h    = blockIdx.y % NH;

    const float* base = qkv + (size_t)b * SEQ * QKV_N + h * HD;

    const uint32_t offA = (uint32_t)(lane & 15) * (KSTR * 2) + ((lane & 16) ? 16 : 0);
    const uint32_t offB = (uint32_t)(((lane & 16) >> 1) + (lane & 7)) * (KSTR * 2)
                        + ((lane & 8) ? 16 : 0);

    // loader mapping: row = tid/2, 32-col half
    const int lr = tid >> 1;
    const int lc = (tid & 1) * 32;
    const uint32_t stoff = (uint32_t)lr * (KSTR * 2) + lc * 2;   // byte offset

    // ---- stage Q (scaled, split) into buf0 Kh/Kl, pull A-frags ----
    {
        const float* qp = base + (size_t)(qt + lr) * QKV_N + lc;
#pragma unroll
        for (int j = 0; j < 8; j++) {
            float4 v = *(const float4*)(qp + j * 4);
            uint32_t h0, l0, h1, l1;
            split_pair(v.x * 0.125f, v.y * 0.125f, h0, l0);
            split_pair(v.z * 0.125f, v.w * 0.125f, h1, l1);
            *(uint2*)(smraw + stoff + j * 8)       = make_uint2(h0, h1);
            *(uint2*)(smraw + ASZ + stoff + j * 8) = make_uint2(l0, l1);
        }
    }
    __syncthreads();

    uint32_t qh[4][4], ql[4][4];
#pragma unroll
    for (int ks = 0; ks < 4; ks++) {
        uint32_t a = (uint32_t)(w * 16) * (KSTR * 2) + ks * 32 + offA;
        LDX4(qh[ks], sb + a);
        LDX4(ql[ks], sb + ASZ + a);
    }
    __syncthreads();

    // ---- prefetch tile 0, stage into buf0, prefetch tile 1 ----
    const float* kbase = base + DIM + (size_t)lr * QKV_N + lc;
    float4 rk[8], rv[8];
#pragma unroll
    for (int j = 0; j < 8; j++) {
        rk[j] = *(const float4*)(kbase + j * 4);
        rv[j] = *(const float4*)(kbase + DIM + j * 4);
    }

    auto stage = [&](int buf) {
        char* p = smraw + buf * BUFSZ + stoff;
#pragma unroll
        for (int j = 0; j < 8; j++) {
            uint32_t h0, lo0, h1, lo1;
            split_pair(rk[j].x, rk[j].y, h0, lo0);
            split_pair(rk[j].z, rk[j].w, h1, lo1);
            *(uint2*)(p + j * 8)           = make_uint2(h0, h1);     // Kh
            *(uint2*)(p + ASZ + j * 8)     = make_uint2(lo0, lo1);   // Kl
            split_pair(rv[j].x, rv[j].y, h0, lo0);
            split_pair(rv[j].z, rv[j].w, h1, lo1);
            *(uint2*)(p + 2 * ASZ + j * 8) = make_uint2(h0, h1);     // Vh
            *(uint2*)(p + 3 * ASZ + j * 8) = make_uint2(lo0, lo1);   // Vl
        }
    };

    stage(0);
#pragma unroll
    for (int j = 0; j < 8; j++) {
        rk[j] = *(const float4*)(kbase + 64 * QKV_N + j * 4);
        rv[j] = *(const float4*)(kbase + 64 * QKV_N + DIM + j * 4);
    }
    __syncthreads();

    float oacc[8][4];
#pragma unroll
    for (int u = 0; u < 8; u++)
#pragma unroll
        for (int j = 0; j < 4; j++) oacc[u][j] = 0.f;
    float m0 = -1e30f, m1 = -1e30f, l0 = 0.f, l1 = 0.f;

    const int NT = SEQ / 64;
    for (int kt = 0; kt < NT; kt++) {
        const uint32_t bb  = sb + (uint32_t)((kt & 1) * BUFSZ);
        const uint32_t uKh = bb, uKl = bb + ASZ;
        const uint32_t uVh = bb + 2 * ASZ, uVl = bb + 3 * ASZ;

        // ---- S = Q @ K^T (3-term) ----
        float sacc[8][4];
#pragma unroll
        for (int u = 0; u < 8; u++)
#pragma unroll
            for (int j = 0; j < 4; j++) sacc[u][j] = 0.f;

#pragma unroll
        for (int ks = 0; ks < 4; ks++) {
#pragma unroll
            for (int np = 0; np < 4; np++) {
                uint32_t kh[4], kl[4];
                uint32_t a = (uint32_t)(np * 16) * (KSTR * 2) + ks * 32 + offB;
                LDX4(kh, uKh + a);
                LDX4(kl, uKl + a);
                const int u = np * 2;
                MMA_BF16(sacc[u],     qh[ks], kh[0], kh[1]);
                MMA_BF16(sacc[u],     qh[ks], kl[0], kl[1]);
                MMA_BF16(sacc[u],     ql[ks], kh[0], kh[1]);
                MMA_BF16(sacc[u + 1], qh[ks], kh[2], kh[3]);
                MMA_BF16(sacc[u + 1], qh[ks], kl[2], kl[3]);
                MMA_BF16(sacc[u + 1], ql[ks], kh[2], kh[3]);
            }
        }

        // ---- online softmax ----
        float mt0 = -1e30f, mt1 = -1e30f;
#pragma unroll
        for (int u = 0; u < 8; u++) {
            mt0 = fmaxf(mt0, fmaxf(sacc[u][0], sacc[u][1]));
            mt1 = fmaxf(mt1, fmaxf(sacc[u][2], sacc[u][3]));
        }
        mt0 = fmaxf(mt0, __shfl_xor_sync(0xffffffffu, mt0, 1));
        mt0 = fmaxf(mt0, __shfl_xor_sync(0xffffffffu, mt0, 2));
        mt1 = fmaxf(mt1, __shfl_xor_sync(0xffffffffu, mt1, 1));
        mt1 = fmaxf(mt1, __shfl_xor_sync(0xffffffffu, mt1, 2));

        const float mn0 = fmaxf(m0, mt0);
        const float mn1 = fmaxf(m1, mt1);
        const float a0 = __expf(m0 - mn0);
        const float a1 = __expf(m1 - mn1);

        float ls0 = 0.f, ls1 = 0.f;
#pragma unroll
        for (int u = 0; u < 8; u++) {
            sacc[u][0] = __expf(sacc[u][0] - mn0);
            sacc[u][1] = __expf(sacc[u][1] - mn0);
            sacc[u][2] = __expf(sacc[u][2] - mn1);
            sacc[u][3] = __expf(sacc[u][3] - mn1);
            ls0 += sacc[u][0] + sacc[u][1];
            ls1 += sacc[u][2] + sacc[u][3];
        }
        ls0 += __shfl_xor_sync(0xffffffffu, ls0, 1);
        ls0 += __shfl_xor_sync(0xffffffffu, ls0, 2);
        ls1 += __shfl_xor_sync(0xffffffffu, ls1, 1);
        ls1 += __shfl_xor_sync(0xffffffffu, ls1, 2);
        l0 = l0 * a0 + ls0;  m0 = mn0;
        l1 = l1 * a1 + ls1;  m1 = mn1;

#pragma unroll
        for (int u = 0; u < 8; u++) {
            oacc[u][0] *= a0; oacc[u][1] *= a0;
            oacc[u][2] *= a1; oacc[u][3] *= a1;
        }

        // ---- stage next tile into alternate buffer; prefetch kt+2 ----
        if (kt + 1 < NT) {
            stage((kt + 1) & 1);
            if (kt + 2 < NT) {
                const float* np = kbase + (size_t)(kt + 2) * 64 * QKV_N;
#pragma unroll
                for (int j = 0; j < 8; j++) {
                    rk[j] = *(const float4*)(np + j * 4);
                    rv[j] = *(const float4*)(np + DIM + j * 4);
                }
            }
        }

        // ---- pack P into A-frags (hi/lo) ----
        uint32_t pah[4][4], pal[4][4];
#pragma unroll
        for (int t = 0; t < 4; t++) {
            split_pair(sacc[2 * t][0],     sacc[2 * t][1],     pah[t][0], pal[t][0]);
            split_pair(sacc[2 * t][2],     sacc[2 * t][3],     pah[t][1], pal[t][1]);
            split_pair(sacc[2 * t + 1][0], sacc[2 * t + 1][1], pah[t][2], pal[t][2]);
            split_pair(sacc[2 * t + 1][2], sacc[2 * t + 1][3], pah[t][3], pal[t][3]);
        }

        // ---- O += P @ V (3-term; V via ldmatrix.trans) ----
#pragma unroll
        for (int t = 0; t < 4; t++) {
#pragma unroll
            for (int nd = 0; nd < 4; nd++) {
                uint32_t vh[4], vl[4];
                uint32_t a = (uint32_t)(t * 16) * (KSTR * 2) + nd * 32 + offB;
                LDX4T(vh, uVh + a);
                LDX4T(vl, uVl + a);
                const int u = nd * 2;
                MMA_BF16(oacc[u],     pah[t], vh[0], vh[2]);
                MMA_BF16(oacc[u],     pah[t], vl[0], vl[2]);
                MMA_BF16(oacc[u],     pal[t], vh[0], vh[2]);
                MMA_BF16(oacc[u + 1], pah[t], vh[1], vh[3]);
                MMA_BF16(oacc[u + 1], pah[t], vl[1], vl[3]);
                MMA_BF16(oacc[u + 1], pal[t], vh[1], vh[3]);
            }
        }
        __syncthreads();
    }

    // ---- epilogue ----
    const float inv0 = 1.f / l0;
    const float inv1 = 1.f / l1;
    const int er = lane >> 2;
    const int ec = (lane & 3) * 2;
    const size_t tok0 = (size_t)b * SEQ + qt + w * 16 + er;
    const int colb = h * HD + ec;
#pragma unroll
    for (int u = 0; u < 8; u++) {
        const int col = colb + u * 8;
        uint32_t hp, lp;
        split_pair(oacc[u][0] * inv0, oacc[u][1] * inv0, hp, lp);
        *(uint32_t*)(oh + tok0 * DIM + col) = hp;
        *(uint32_t*)(ol + tok0 * DIM + col) = lp;
        split_pair(oacc[u][2] * inv1, oacc[u][3] * inv1, hp, lp);
        *(uint32_t*)(oh + (tok0 + 8) * DIM + col) = hp;
        *(uint32_t*)(ol + (tok0 + 8) * DIM + col) = lp;
    }
}

extern "C" void kernel_launch(void* const* d_in, const int* in_sizes, int n_in,
                              void* d_out, int out_size)
{
    const float* x      = (const float*)d_in[0];
    const float* qkv_w  = (const float*)d_in[1];
    const float* qkv_b  = (const float*)d_in[2];
    const float* proj_w = (const float*)d_in[3];
    const float* proj_b = (const float*)d_in[4];
    float* out = (float*)d_out;

    float* qkv;
    __nv_bfloat16 *xh, *xl, *qwh, *qwl, *pwh, *pwl, *ah, *al;
    cudaGetSymbolAddress((void**)&qkv, g_qkv);
    cudaGetSymbolAddress((void**)&xh,  g_xh);
    cudaGetSymbolAddress((void**)&xl,  g_xl);
    cudaGetSymbolAddress((void**)&qwh, g_qwh);
    cudaGetSymbolAddress((void**)&qwl, g_qwl);
    cudaGetSymbolAddress((void**)&pwh, g_pwh);
    cudaGetSymbolAddress((void**)&pwl, g_pwl);
    cudaGetSymbolAddress((void**)&ah,  g_ah);
    cudaGetSymbolAddress((void**)&al,  g_al);

    cudaFuncSetAttribute(attn_mma,
                         cudaFuncAttributeMaxDynamicSharedMemorySize, ATTN_SMEM);

    // splits
    const int nx = M_TOT * DIM, nqw = QKV_N * DIM, npw = DIM * DIM;
    split_kernel<<<(nx / 4 + 255) / 256, 256>>>(x, xh, xl, nx);
    split_kernel<<<(nqw / 4 + 255) / 256, 256>>>(qkv_w, qwh, qwl, nqw);
    split_kernel<<<(npw / 4 + 255) / 256, 256>>>(proj_w, pwh, pwl, npw);

    // QKV projection: [8192, 2304]
    gemm_bf16x3<<<dim3(QKV_N / 128, M_TOT / 128), 256>>>(
        xh, xl, qwh, qwl, qkv_b, qkv, QKV_N, DIM);

    // Attention (tensor-core, pipelined) -> bf16 hi/lo
    attn_mma<<<dim3(SEQ / 64, BATCH * NH), 128, ATTN_SMEM>>>(qkv, ah, al);

    // Output projection: [8192, 768]
    gemm_bf16x3<<<dim3(DIM / 128, M_TOT / 128), 256>>>(
        ah, al, pwh, pwl, proj_b, out, DIM, DIM);
}